// round 2
// baseline (speedup 1.0000x reference)
#include <cuda_runtime.h>
#include <cstdint>

// Problem constants
#define TT      64
#define NN      8192
#define FF      256
#define HH      256
#define KK2     512          // F + H fused K dimension
#define MT      64           // rows per CTA
#define NCTA    (NN / MT)    // 128
#define NTH     256
#define ASTR    516          // SMEM A row stride (512 + 4 pad, keeps 16B align, kills bank conflicts)
#define KCH     16           // K chunk
#define LN_EPS  1e-5f

// Scratch: transposed fused weight Wt[k][c] = (k<F ? W_ih[c][k] : W_hh[c][k-F]), and fused bias.
__device__ float g_Wt[KK2 * HH];
__device__ float g_bc[HH];

// ---------- packed f32x2 helpers (ptxas won't auto-fuse; PTX only) ----------
__device__ __forceinline__ unsigned long long pk2(float lo, float hi) {
    unsigned long long r;
    asm("mov.b64 %0, {%1, %2};" : "=l"(r) : "f"(lo), "f"(hi));
    return r;
}
__device__ __forceinline__ void upk2(unsigned long long v, float &lo, float &hi) {
    asm("mov.b64 {%0, %1}, %2;" : "=f"(lo), "=f"(hi) : "l"(v));
}
__device__ __forceinline__ unsigned long long ffma2(unsigned long long a,
                                                    unsigned long long b,
                                                    unsigned long long c) {
    unsigned long long d;
    asm("fma.rn.f32x2 %0, %1, %2, %3;" : "=l"(d) : "l"(a), "l"(b), "l"(c));
    return d;
}

// ---------- prep: transpose weights into k-major fused layout, fold biases ----------
__global__ void prep_kernel(const float* __restrict__ W_ih, const float* __restrict__ W_hh,
                            const float* __restrict__ b_ih, const float* __restrict__ b_hh) {
    int idx = blockIdx.x * blockDim.x + threadIdx.x;
    int stride = gridDim.x * blockDim.x;
    for (int i = idx; i < KK2 * HH; i += stride) {
        int k = i >> 8;      // / 256
        int c = i & 255;
        g_Wt[i] = (k < FF) ? W_ih[c * FF + k] : W_hh[c * HH + (k - FF)];
    }
    if (idx < HH) g_bc[idx] = b_ih[idx] + b_hh[idx];
}

// ---------- tile GEMM: acc[4][8 f32x2] += A(64 x K) * Wt(K x 256) ----------
// A in SMEM (row stride ASTR), Wt streamed from L2 through double-buffered SMEM chunks.
__device__ __forceinline__ void gemm_tile(const float* __restrict__ sA,
                                          float* __restrict__ sW0,
                                          float* __restrict__ sW1,
                                          int nchunks, int row0, int col0, int tid,
                                          unsigned long long (&acc)[4][8]) {
#pragma unroll
    for (int r = 0; r < 4; ++r)
#pragma unroll
        for (int p = 0; p < 8; ++p) acc[r][p] = 0ull;

    // stage chunk 0
    {
        const float4* src = (const float4*)g_Wt;
        float4 pre[4];
#pragma unroll
        for (int j = 0; j < 4; ++j) pre[j] = src[tid + NTH * j];
#pragma unroll
        for (int j = 0; j < 4; ++j) ((float4*)sW0)[tid + NTH * j] = pre[j];
    }
    __syncthreads();

    for (int ch = 0; ch < nchunks; ++ch) {
        // prefetch next chunk to registers (hides L2 latency under the compute below)
        float4 nxt[4];
        if (ch + 1 < nchunks) {
            const float4* src = (const float4*)(g_Wt + (size_t)(ch + 1) * KCH * HH);
#pragma unroll
            for (int j = 0; j < 4; ++j) nxt[j] = src[tid + NTH * j];
        }
        const float* bw = (ch & 1) ? sW1 : sW0;
        const int kbase = ch * KCH;
#pragma unroll
        for (int kk = 0; kk < KCH; ++kk) {
            const int kg = kbase + kk;
            float a0 = sA[(row0 + 0) * ASTR + kg];
            float a1 = sA[(row0 + 1) * ASTR + kg];
            float a2 = sA[(row0 + 2) * ASTR + kg];
            float a3 = sA[(row0 + 3) * ASTR + kg];
            unsigned long long ad0 = pk2(a0, a0);
            unsigned long long ad1 = pk2(a1, a1);
            unsigned long long ad2 = pk2(a2, a2);
            unsigned long long ad3 = pk2(a3, a3);
            const ulonglong2* bp = (const ulonglong2*)(bw + kk * HH + col0);
            unsigned long long b[8];
#pragma unroll
            for (int q = 0; q < 4; ++q) {
                ulonglong2 v = bp[q];
                b[2 * q] = v.x; b[2 * q + 1] = v.y;
            }
#pragma unroll
            for (int p = 0; p < 8; ++p) acc[0][p] = ffma2(ad0, b[p], acc[0][p]);
#pragma unroll
            for (int p = 0; p < 8; ++p) acc[1][p] = ffma2(ad1, b[p], acc[1][p]);
#pragma unroll
            for (int p = 0; p < 8; ++p) acc[2][p] = ffma2(ad2, b[p], acc[2][p]);
#pragma unroll
            for (int p = 0; p < 8; ++p) acc[3][p] = ffma2(ad3, b[p], acc[3][p]);
        }
        if (ch + 1 < nchunks) {
            float* bn = ((ch + 1) & 1) ? sW1 : sW0;
#pragma unroll
            for (int j = 0; j < 4; ++j) ((float4*)bn)[tid + NTH * j] = nxt[j];
        }
        __syncthreads();
    }
}

// ---------- main persistent recurrence kernel ----------
__global__ void __launch_bounds__(NTH, 1)
rnn_kernel(const float* __restrict__ X, const float* __restrict__ ln_w,
           const float* __restrict__ ln_b, float* __restrict__ out) {
    extern __shared__ float smem[];
    float* sA   = smem;                    // [MT][ASTR]  cols 0..255 = x_t, 256..511 = h
    float* sW0  = sA + MT * ASTR;          // [KCH][HH]
    float* sW1  = sW0 + KCH * HH;          // [KCH][HH]
    float* sLNw = sW1 + KCH * HH;          // [HH]
    float* sLNb = sLNw + HH;               // [HH]
    float* sBC  = sLNb + HH;               // [HH]

    const int tid  = threadIdx.x;
    const int tx   = tid & 15;
    const int ty   = tid >> 4;
    const int row0 = ty * 4;               // this thread's 4 rows
    const int col0 = tx * 16;              // this thread's 16 cols
    const size_t gr0 = (size_t)blockIdx.x * MT;

    for (int i = tid; i < HH; i += NTH) {
        sLNw[i] = ln_w[i];
        sLNb[i] = ln_b[i];
        sBC[i]  = g_bc[i];
    }
    // (first __syncthreads happens inside gemm_tile / after x load)

    unsigned long long acc[4][8];

    // ---- prologue: h0 = x0 @ W_ih^T + b_ih + b_hh   (NO relu, NOT an output) ----
    {
        const float4* xs = (const float4*)(X + gr0 * FF);
#pragma unroll
        for (int j = 0; j < 16; ++j) {
            int q = tid + NTH * j;                     // 0..4095 float4s
            ((float4*)(sA + (q >> 6) * ASTR))[q & 63] = xs[q];
        }
    }
    __syncthreads();
    gemm_tile(sA, sW0, sW1, FF / KCH, row0, col0, tid, acc);   // K = 256 (x part only)
#pragma unroll
    for (int r = 0; r < 4; ++r) {
        float v[16];
#pragma unroll
        for (int p = 0; p < 8; ++p) {
            float lo, hi; upk2(acc[r][p], lo, hi);
            v[2 * p]     = lo + sBC[col0 + 2 * p];
            v[2 * p + 1] = hi + sBC[col0 + 2 * p + 1];
        }
        float* hrow = sA + (row0 + r) * ASTR + FF + col0;
#pragma unroll
        for (int j = 0; j < 4; ++j)
            ((float4*)hrow)[j] = make_float4(v[4 * j], v[4 * j + 1], v[4 * j + 2], v[4 * j + 3]);
    }
    __syncthreads();

    const float inv256 = 1.0f / 256.0f;

    // ---- 64 recurrent steps, fully fused: GEMM + bias + relu + h update + LayerNorm ----
    for (int t = 0; t < TT; ++t) {
        const float4* xs = (const float4*)(X + ((size_t)t * NN + gr0) * FF);
#pragma unroll
        for (int j = 0; j < 16; ++j) {
            int q = tid + NTH * j;
            ((float4*)(sA + (q >> 6) * ASTR))[q & 63] = xs[q];
        }
        __syncthreads();

        gemm_tile(sA, sW0, sW1, KK2 / KCH, row0, col0, tid, acc);   // K = 512
        // gemm_tile ends with __syncthreads(): all sA reads complete -> safe to overwrite h

#pragma unroll
        for (int r = 0; r < 4; ++r) {
            float v[16];
            float s = 0.f, s2 = 0.f;
#pragma unroll
            for (int p = 0; p < 8; ++p) {
                float lo, hi; upk2(acc[r][p], lo, hi);
                lo = fmaxf(lo + sBC[col0 + 2 * p], 0.f);
                hi = fmaxf(hi + sBC[col0 + 2 * p + 1], 0.f);
                v[2 * p] = lo; v[2 * p + 1] = hi;
                s  += lo + hi;
                s2 += lo * lo + hi * hi;
            }
            // new h back to SMEM for next step
            float* hrow = sA + (row0 + r) * ASTR + FF + col0;
#pragma unroll
            for (int j = 0; j < 4; ++j)
                ((float4*)hrow)[j] = make_float4(v[4 * j], v[4 * j + 1], v[4 * j + 2], v[4 * j + 3]);

            // LayerNorm: reduce over the 16 lanes (tx group) covering this row's 256 cols
#pragma unroll
            for (int o = 8; o > 0; o >>= 1) {
                s  += __shfl_xor_sync(0xffffffffu, s,  o, 16);
                s2 += __shfl_xor_sync(0xffffffffu, s2, o, 16);
            }
            float mean = s * inv256;
            float var  = fmaf(-mean, mean, s2 * inv256);
            float rstd = rsqrtf(var + LN_EPS);

            float* orow = out + ((size_t)t * NN + gr0 + row0 + r) * HH + col0;
#pragma unroll
            for (int j = 0; j < 4; ++j) {
                float4 o4;
                o4.x = (v[4 * j + 0] - mean) * rstd * sLNw[col0 + 4 * j + 0] + sLNb[col0 + 4 * j + 0];
                o4.y = (v[4 * j + 1] - mean) * rstd * sLNw[col0 + 4 * j + 1] + sLNb[col0 + 4 * j + 1];
                o4.z = (v[4 * j + 2] - mean) * rstd * sLNw[col0 + 4 * j + 2] + sLNb[col0 + 4 * j + 2];
                o4.w = (v[4 * j + 3] - mean) * rstd * sLNw[col0 + 4 * j + 3] + sLNb[col0 + 4 * j + 3];
                ((float4*)orow)[j] = o4;
            }
        }
        // next iteration's x-load + its __syncthreads separate these h writes from the next GEMM's reads
    }
}

#define SMEM_BYTES ((MT * ASTR + 2 * KCH * HH + 3 * HH) * (int)sizeof(float))  // 167936

extern "C" void kernel_launch(void* const* d_in, const int* in_sizes, int n_in,
                              void* d_out, int out_size) {
    const float* X    = (const float*)d_in[0];
    const float* W_ih = (const float*)d_in[1];
    const float* W_hh = (const float*)d_in[2];
    const float* b_ih = (const float*)d_in[3];
    const float* b_hh = (const float*)d_in[4];
    const float* ln_w = (const float*)d_in[5];
    const float* ln_b = (const float*)d_in[6];
    float* out = (float*)d_out;

    cudaFuncSetAttribute(rnn_kernel, cudaFuncAttributeMaxDynamicSharedMemorySize, SMEM_BYTES);

    prep_kernel<<<64, NTH>>>(W_ih, W_hh, b_ih, b_hh);
    rnn_kernel<<<NCTA, NTH, SMEM_BYTES>>>(X, ln_w, ln_b, out);
}

// round 3
// speedup vs baseline: 2.9999x; 2.9999x over previous
#include <cuda_runtime.h>
#include <cstdint>

// Problem constants
#define TT      64
#define NN      8192
#define FF      256
#define HH      256
#define KK2     512          // F + H fused K dimension
#define MT      64           // rows per CTA
#define NCTA    (NN / MT)    // 128
#define NTH     256
#define ASTR    516          // SMEM A row stride (512 + 4 pad)
#define KCH     16           // K chunk
#define LN_EPS  1e-5f

// Scratch: transposed fused weight Wt[k][c] = (k<F ? W_ih[c][k] : W_hh[c][k-F]), fused bias.
__device__ float g_Wt[KK2 * HH];
__device__ float g_bc[HH];

// ---------- packed f32x2 helpers ----------
__device__ __forceinline__ unsigned long long pk2(float lo, float hi) {
    unsigned long long r;
    asm("mov.b64 %0, {%1, %2};" : "=l"(r) : "f"(lo), "f"(hi));
    return r;
}
__device__ __forceinline__ void upk2(unsigned long long v, float &lo, float &hi) {
    asm("mov.b64 {%0, %1}, %2;" : "=f"(lo), "=f"(hi) : "l"(v));
}
__device__ __forceinline__ unsigned long long ffma2(unsigned long long a,
                                                    unsigned long long b,
                                                    unsigned long long c) {
    unsigned long long d;
    asm("fma.rn.f32x2 %0, %1, %2, %3;" : "=l"(d) : "l"(a), "l"(b), "l"(c));
    return d;
}

// ---------- prep: transpose weights into k-major fused layout, fold biases ----------
__global__ void prep_kernel(const float* __restrict__ W_ih, const float* __restrict__ W_hh,
                            const float* __restrict__ b_ih, const float* __restrict__ b_hh) {
    int idx = blockIdx.x * blockDim.x + threadIdx.x;
    int stride = gridDim.x * blockDim.x;
    for (int i = idx; i < KK2 * HH; i += stride) {
        int k = i >> 8;
        int c = i & 255;
        g_Wt[i] = (k < FF) ? W_ih[c * FF + k] : W_hh[c * HH + (k - FF)];
    }
    if (idx < HH) g_bc[idx] = b_ih[idx] + b_hh[idx];
}

// ---------- tile GEMM: acc[4][8 f32x2] += A(64 x K) * Wt(K x 256) ----------
// Thread (tx, ty) owns rows row0..row0+3 and cols {colb + 64*q + 0..3 : q=0..3}.
// colb = tx*4 -> within each 8-lane LDS.128 phase, lanes read consecutive float4s
// (conflict-free) and adjacent lanes (same tx, different ty) read identical
// addresses (2-way broadcast dedup inside the phase).
__device__ __forceinline__ void gemm_tile(const float* __restrict__ sA,
                                          float* __restrict__ sW0,
                                          float* __restrict__ sW1,
                                          int nchunks, int row0, int colb, int tid,
                                          unsigned long long (&acc)[4][8]) {
#pragma unroll
    for (int r = 0; r < 4; ++r)
#pragma unroll
        for (int p = 0; p < 8; ++p) acc[r][p] = 0ull;

    // stage chunk 0
    {
        const float4* src = (const float4*)g_Wt;
        float4 pre[4];
#pragma unroll
        for (int j = 0; j < 4; ++j) pre[j] = src[tid + NTH * j];
#pragma unroll
        for (int j = 0; j < 4; ++j) ((float4*)sW0)[tid + NTH * j] = pre[j];
    }
    __syncthreads();

    for (int ch = 0; ch < nchunks; ++ch) {
        // prefetch next chunk into registers (L2-latency hiding)
        float4 nxt[4];
        if (ch + 1 < nchunks) {
            const float4* src = (const float4*)(g_Wt + (size_t)(ch + 1) * KCH * HH);
#pragma unroll
            for (int j = 0; j < 4; ++j) nxt[j] = src[tid + NTH * j];
        }
        const float* bw = (ch & 1) ? sW1 : sW0;
        const int kbase = ch * KCH;
#pragma unroll
        for (int kk = 0; kk < KCH; ++kk) {
            const int kg = kbase + kk;
            float a0 = sA[(row0 + 0) * ASTR + kg];
            float a1 = sA[(row0 + 1) * ASTR + kg];
            float a2 = sA[(row0 + 2) * ASTR + kg];
            float a3 = sA[(row0 + 3) * ASTR + kg];
            unsigned long long ad0 = pk2(a0, a0);
            unsigned long long ad1 = pk2(a1, a1);
            unsigned long long ad2 = pk2(a2, a2);
            unsigned long long ad3 = pk2(a3, a3);
            unsigned long long b[8];
#pragma unroll
            for (int q = 0; q < 4; ++q) {
                ulonglong2 v = *(const ulonglong2*)(bw + kk * HH + colb + 64 * q);
                b[2 * q] = v.x; b[2 * q + 1] = v.y;
            }
#pragma unroll
            for (int p = 0; p < 8; ++p) acc[0][p] = ffma2(ad0, b[p], acc[0][p]);
#pragma unroll
            for (int p = 0; p < 8; ++p) acc[1][p] = ffma2(ad1, b[p], acc[1][p]);
#pragma unroll
            for (int p = 0; p < 8; ++p) acc[2][p] = ffma2(ad2, b[p], acc[2][p]);
#pragma unroll
            for (int p = 0; p < 8; ++p) acc[3][p] = ffma2(ad3, b[p], acc[3][p]);
        }
        if (ch + 1 < nchunks) {
            float* bn = ((ch + 1) & 1) ? sW1 : sW0;
#pragma unroll
            for (int j = 0; j < 4; ++j) ((float4*)bn)[tid + NTH * j] = nxt[j];
        }
        __syncthreads();
    }
}

// ---------- main persistent recurrence kernel ----------
__global__ void __launch_bounds__(NTH, 1)
rnn_kernel(const float* __restrict__ X, const float* __restrict__ ln_w,
           const float* __restrict__ ln_b, float* __restrict__ out) {
    extern __shared__ float smem[];
    float* sA   = smem;                    // [MT][ASTR]  cols 0..255 = x_t, 256..511 = h
    float* sW0  = sA + MT * ASTR;          // [KCH][HH]
    float* sW1  = sW0 + KCH * HH;          // [KCH][HH]
    float* sLNw = sW1 + KCH * HH;          // [HH]
    float* sLNb = sLNw + HH;               // [HH]
    float* sBC  = sLNb + HH;               // [HH]

    const int tid  = threadIdx.x;
    const int lane = tid & 31;
    const int wid  = tid >> 5;
    const int tx   = lane >> 1;            // 0..15 (lane pairs share tx -> B bcast dedup)
    const int pr   = lane & 1;
    const int ty   = wid * 2 + pr;         // 0..15
    const int row0 = ty * 4;               // this thread's 4 rows
    const int colb = tx * 4;               // base col; groups at colb + 64*q, q=0..3
    const size_t gr0 = (size_t)blockIdx.x * MT;

    for (int i = tid; i < HH; i += NTH) {
        sLNw[i] = ln_w[i];
        sLNb[i] = ln_b[i];
        sBC[i]  = g_bc[i];
    }

    unsigned long long acc[4][8];

    // ---- prologue: h0 = x0 @ W_ih^T + b_ih + b_hh   (NO relu, NOT an output) ----
    {
        const float4* xs = (const float4*)(X + gr0 * FF);
#pragma unroll
        for (int j = 0; j < 16; ++j) {
            int q = tid + NTH * j;
            ((float4*)(sA + (q >> 6) * ASTR))[q & 63] = xs[q];
        }
    }
    __syncthreads();
    gemm_tile(sA, sW0, sW1, FF / KCH, row0, colb, tid, acc);   // K = 256 (x part only)
#pragma unroll
    for (int r = 0; r < 4; ++r) {
        float* hrow = sA + (row0 + r) * ASTR + FF;
#pragma unroll
        for (int q = 0; q < 4; ++q) {
            int c = colb + 64 * q;
            float v0, v1, v2, v3;
            upk2(acc[r][2 * q],     v0, v1);
            upk2(acc[r][2 * q + 1], v2, v3);
            v0 += sBC[c + 0]; v1 += sBC[c + 1];
            v2 += sBC[c + 2]; v3 += sBC[c + 3];
            *(float4*)(hrow + c) = make_float4(v0, v1, v2, v3);
        }
    }
    __syncthreads();

    const float inv256 = 1.0f / 256.0f;

    // ---- 64 recurrent steps: GEMM + bias + relu + h update + LayerNorm, fused ----
    for (int t = 0; t < TT; ++t) {
        const float4* xs = (const float4*)(X + ((size_t)t * NN + gr0) * FF);
#pragma unroll
        for (int j = 0; j < 16; ++j) {
            int q = tid + NTH * j;
            ((float4*)(sA + (q >> 6) * ASTR))[q & 63] = xs[q];
        }
        __syncthreads();

        gemm_tile(sA, sW0, sW1, KK2 / KCH, row0, colb, tid, acc);   // K = 512
        // gemm_tile ends with __syncthreads(): all sA reads done -> safe to overwrite h

#pragma unroll
        for (int r = 0; r < 4; ++r) {
            float v[16];
            float s = 0.f, s2 = 0.f;
#pragma unroll
            for (int q = 0; q < 4; ++q) {
                int c = colb + 64 * q;
                float v0, v1, v2, v3;
                upk2(acc[r][2 * q],     v0, v1);
                upk2(acc[r][2 * q + 1], v2, v3);
                v0 = fmaxf(v0 + sBC[c + 0], 0.f);
                v1 = fmaxf(v1 + sBC[c + 1], 0.f);
                v2 = fmaxf(v2 + sBC[c + 2], 0.f);
                v3 = fmaxf(v3 + sBC[c + 3], 0.f);
                v[4 * q + 0] = v0; v[4 * q + 1] = v1;
                v[4 * q + 2] = v2; v[4 * q + 3] = v3;
                s  += (v0 + v1) + (v2 + v3);
                s2 += (v0 * v0 + v1 * v1) + (v2 * v2 + v3 * v3);
            }
            // new h back to SMEM for next step
            float* hrow = sA + (row0 + r) * ASTR + FF;
#pragma unroll
            for (int q = 0; q < 4; ++q)
                *(float4*)(hrow + colb + 64 * q) =
                    make_float4(v[4 * q], v[4 * q + 1], v[4 * q + 2], v[4 * q + 3]);

            // LayerNorm: reduce across the 16 same-parity lanes (tx groups) of this row
#pragma unroll
            for (int o = 2; o <= 16; o <<= 1) {
                s  += __shfl_xor_sync(0xffffffffu, s,  o);
                s2 += __shfl_xor_sync(0xffffffffu, s2, o);
            }
            float mean = s * inv256;
            float var  = fmaf(-mean, mean, s2 * inv256);
            float rstd = rsqrtf(var + LN_EPS);

            float* orow = out + ((size_t)t * NN + gr0 + row0 + r) * HH;
#pragma unroll
            for (int q = 0; q < 4; ++q) {
                int c = colb + 64 * q;
                float4 o4;
                o4.x = (v[4 * q + 0] - mean) * rstd * sLNw[c + 0] + sLNb[c + 0];
                o4.y = (v[4 * q + 1] - mean) * rstd * sLNw[c + 1] + sLNb[c + 1];
                o4.z = (v[4 * q + 2] - mean) * rstd * sLNw[c + 2] + sLNb[c + 2];
                o4.w = (v[4 * q + 3] - mean) * rstd * sLNw[c + 3] + sLNb[c + 3];
                *(float4*)(orow + c) = o4;
            }
        }
        // next iteration's x-load + its __syncthreads separate these h writes
        // from the next GEMM's reads
    }
}

#define SMEM_BYTES ((MT * ASTR + 2 * KCH * HH + 3 * HH) * (int)sizeof(float))  // 167936

extern "C" void kernel_launch(void* const* d_in, const int* in_sizes, int n_in,
                              void* d_out, int out_size) {
    const float* X    = (const float*)d_in[0];
    const float* W_ih = (const float*)d_in[1];
    const float* W_hh = (const float*)d_in[2];
    const float* b_ih = (const float*)d_in[3];
    const float* b_hh = (const float*)d_in[4];
    const float* ln_w = (const float*)d_in[5];
    const float* ln_b = (const float*)d_in[6];
    float* out = (float*)d_out;

    cudaFuncSetAttribute(rnn_kernel, cudaFuncAttributeMaxDynamicSharedMemorySize, SMEM_BYTES);

    prep_kernel<<<64, NTH>>>(W_ih, W_hh, b_ih, b_hh);
    rnn_kernel<<<NCTA, NTH, SMEM_BYTES>>>(X, ln_w, ln_b, out);
}

// round 5
// speedup vs baseline: 3.0008x; 1.0003x over previous
#include <cuda_runtime.h>
#include <cstdint>

// Problem constants
#define TT      64
#define NN      8192
#define FF      256
#define HH      256
#define KK2     512          // F + H fused K dimension
#define MT      64           // rows per CTA
#define NCTA    (NN / MT)    // 128
#define NTH     256
#define ASTR    516          // SMEM A row stride (512 + 4 pad)
#define KCH     16           // K chunk
#define LN_EPS  1e-5f

// Scratch: transposed fused weight Wt[k][c] = (k<F ? W_ih[c][k] : W_hh[c][k-F]), fused bias.
__device__ float g_Wt[KK2 * HH];
__device__ float g_bc[HH];

// ---------- packed f32x2 helpers ----------
__device__ __forceinline__ unsigned long long pk2(float lo, float hi) {
    unsigned long long r;
    asm("mov.b64 %0, {%1, %2};" : "=l"(r) : "f"(lo), "f"(hi));
    return r;
}
__device__ __forceinline__ void upk2(unsigned long long v, float &lo, float &hi) {
    asm("mov.b64 {%0, %1}, %2;" : "=f"(lo), "=f"(hi) : "l"(v));
}
__device__ __forceinline__ unsigned long long ffma2(unsigned long long a,
                                                    unsigned long long b,
                                                    unsigned long long c) {
    unsigned long long d;
    asm("fma.rn.f32x2 %0, %1, %2, %3;" : "=l"(d) : "l"(a), "l"(b), "l"(c));
    return d;
}

// ---------- prep: transpose weights into k-major fused layout, fold biases ----------
__global__ void prep_kernel(const float* __restrict__ W_ih, const float* __restrict__ W_hh,
                            const float* __restrict__ b_ih, const float* __restrict__ b_hh) {
    int idx = blockIdx.x * blockDim.x + threadIdx.x;
    int stride = gridDim.x * blockDim.x;
    for (int i = idx; i < KK2 * HH; i += stride) {
        int k = i >> 8;
        int c = i & 255;
        g_Wt[i] = (k < FF) ? W_ih[c * FF + k] : W_hh[c * HH + (k - FF)];
    }
    if (idx < HH) g_bc[idx] = b_ih[idx] + b_hh[idx];
}

// ---------- tile GEMM: acc[4][8 f32x2] += A(64 x K) * Wt(K x 256) ----------
// Thread (tx, ty) owns rows row0..row0+3 and cols {colb + 64*q + 0..3 : q=0..3}.
// colb = tx*4 -> within each 8-lane LDS.128 phase, lanes read consecutive float4s
// (conflict-free) and adjacent lanes (same tx, different ty) read identical
// addresses (2-way broadcast dedup inside the phase).
__device__ __forceinline__ void gemm_tile(const float* __restrict__ sA,
                                          float* __restrict__ sW0,
                                          float* __restrict__ sW1,
                                          int nchunks, int row0, int colb, int tid,
                                          unsigned long long (&acc)[4][8]) {
#pragma unroll
    for (int r = 0; r < 4; ++r)
#pragma unroll
        for (int p = 0; p < 8; ++p) acc[r][p] = 0ull;

    // stage chunk 0
    {
        const float4* src = (const float4*)g_Wt;
        float4 pre[4];
#pragma unroll
        for (int j = 0; j < 4; ++j) pre[j] = src[tid + NTH * j];
#pragma unroll
        for (int j = 0; j < 4; ++j) ((float4*)sW0)[tid + NTH * j] = pre[j];
    }
    __syncthreads();

    for (int ch = 0; ch < nchunks; ++ch) {
        // prefetch next chunk into registers (L2-latency hiding)
        float4 nxt[4];
        if (ch + 1 < nchunks) {
            const float4* src = (const float4*)(g_Wt + (size_t)(ch + 1) * KCH * HH);
#pragma unroll
            for (int j = 0; j < 4; ++j) nxt[j] = src[tid + NTH * j];
        }
        const float* bw = (ch & 1) ? sW1 : sW0;
        const int kbase = ch * KCH;
#pragma unroll
        for (int kk = 0; kk < KCH; ++kk) {
            const int kg = kbase + kk;
            float a0 = sA[(row0 + 0) * ASTR + kg];
            float a1 = sA[(row0 + 1) * ASTR + kg];
            float a2 = sA[(row0 + 2) * ASTR + kg];
            float a3 = sA[(row0 + 3) * ASTR + kg];
            unsigned long long ad0 = pk2(a0, a0);
            unsigned long long ad1 = pk2(a1, a1);
            unsigned long long ad2 = pk2(a2, a2);
            unsigned long long ad3 = pk2(a3, a3);
            unsigned long long b[8];
#pragma unroll
            for (int q = 0; q < 4; ++q) {
                ulonglong2 v = *(const ulonglong2*)(bw + kk * HH + colb + 64 * q);
                b[2 * q] = v.x; b[2 * q + 1] = v.y;
            }
#pragma unroll
            for (int p = 0; p < 8; ++p) acc[0][p] = ffma2(ad0, b[p], acc[0][p]);
#pragma unroll
            for (int p = 0; p < 8; ++p) acc[1][p] = ffma2(ad1, b[p], acc[1][p]);
#pragma unroll
            for (int p = 0; p < 8; ++p) acc[2][p] = ffma2(ad2, b[p], acc[2][p]);
#pragma unroll
            for (int p = 0; p < 8; ++p) acc[3][p] = ffma2(ad3, b[p], acc[3][p]);
        }
        if (ch + 1 < nchunks) {
            float* bn = ((ch + 1) & 1) ? sW1 : sW0;
#pragma unroll
            for (int j = 0; j < 4; ++j) ((float4*)bn)[tid + NTH * j] = nxt[j];
        }
        __syncthreads();
    }
}

// ---------- main persistent recurrence kernel ----------
__global__ void __launch_bounds__(NTH, 1)
rnn_kernel(const float* __restrict__ X, const float* __restrict__ ln_w,
           const float* __restrict__ ln_b, float* __restrict__ out) {
    extern __shared__ float smem[];
    float* sA   = smem;                    // [MT][ASTR]  cols 0..255 = x_t, 256..511 = h
    float* sW0  = sA + MT * ASTR;          // [KCH][HH]
    float* sW1  = sW0 + KCH * HH;          // [KCH][HH]
    float* sLNw = sW1 + KCH * HH;          // [HH]
    float* sLNb = sLNw + HH;               // [HH]
    float* sBC  = sLNb + HH;               // [HH]

    const int tid  = threadIdx.x;
    const int lane = tid & 31;
    const int wid  = tid >> 5;
    const int tx   = lane >> 1;            // 0..15 (lane pairs share tx -> B bcast dedup)
    const int pr   = lane & 1;
    const int ty   = wid * 2 + pr;         // 0..15
    const int row0 = ty * 4;               // this thread's 4 rows
    const int colb = tx * 4;               // base col; groups at colb + 64*q, q=0..3
    const size_t gr0 = (size_t)blockIdx.x * MT;

    for (int i = tid; i < HH; i += NTH) {
        sLNw[i] = ln_w[i];
        sLNb[i] = ln_b[i];
        sBC[i]  = g_bc[i];
    }

    unsigned long long acc[4][8];

    // ---- prologue: h0 = x0 @ W_ih^T + b_ih + b_hh   (NO relu, NOT an output) ----
    {
        const float4* xs = (const float4*)(X + gr0 * FF);
#pragma unroll
        for (int j = 0; j < 16; ++j) {
            int q = tid + NTH * j;
            ((float4*)(sA + (q >> 6) * ASTR))[q & 63] = xs[q];
        }
    }
    __syncthreads();
    gemm_tile(sA, sW0, sW1, FF / KCH, row0, colb, tid, acc);   // K = 256 (x part only)
#pragma unroll
    for (int r = 0; r < 4; ++r) {
        float* hrow = sA + (row0 + r) * ASTR + FF;
#pragma unroll
        for (int q = 0; q < 4; ++q) {
            int c = colb + 64 * q;
            float v0, v1, v2, v3;
            upk2(acc[r][2 * q],     v0, v1);
            upk2(acc[r][2 * q + 1], v2, v3);
            v0 += sBC[c + 0]; v1 += sBC[c + 1];
            v2 += sBC[c + 2]; v3 += sBC[c + 3];
            *(float4*)(hrow + c) = make_float4(v0, v1, v2, v3);
        }
    }
    __syncthreads();

    const float inv256 = 1.0f / 256.0f;

    // ---- 64 recurrent steps: GEMM + bias + relu + h update + LayerNorm, fused ----
    for (int t = 0; t < TT; ++t) {
        const float4* xs = (const float4*)(X + ((size_t)t * NN + gr0) * FF);
#pragma unroll
        for (int j = 0; j < 16; ++j) {
            int q = tid + NTH * j;
            ((float4*)(sA + (q >> 6) * ASTR))[q & 63] = xs[q];
        }
        __syncthreads();

        gemm_tile(sA, sW0, sW1, KK2 / KCH, row0, colb, tid, acc);   // K = 512
        // gemm_tile ends with __syncthreads(): all sA reads done -> safe to overwrite h

#pragma unroll
        for (int r = 0; r < 4; ++r) {
            float v[16];
            float s = 0.f, s2 = 0.f;
#pragma unroll
            for (int q = 0; q < 4; ++q) {
                int c = colb + 64 * q;
                float v0, v1, v2, v3;
                upk2(acc[r][2 * q],     v0, v1);
                upk2(acc[r][2 * q + 1], v2, v3);
                v0 = fmaxf(v0 + sBC[c + 0], 0.f);
                v1 = fmaxf(v1 + sBC[c + 1], 0.f);
                v2 = fmaxf(v2 + sBC[c + 2], 0.f);
                v3 = fmaxf(v3 + sBC[c + 3], 0.f);
                v[4 * q + 0] = v0; v[4 * q + 1] = v1;
                v[4 * q + 2] = v2; v[4 * q + 3] = v3;
                s  += (v0 + v1) + (v2 + v3);
                s2 += (v0 * v0 + v1 * v1) + (v2 * v2 + v3 * v3);
            }
            // new h back to SMEM for next step
            float* hrow = sA + (row0 + r) * ASTR + FF;
#pragma unroll
            for (int q = 0; q < 4; ++q)
                *(float4*)(hrow + colb + 64 * q) =
                    make_float4(v[4 * q], v[4 * q + 1], v[4 * q + 2], v[4 * q + 3]);

            // LayerNorm: reduce across the 16 same-parity lanes (tx groups) of this row
#pragma unroll
            for (int o = 2; o <= 16; o <<= 1) {
                s  += __shfl_xor_sync(0xffffffffu, s,  o);
                s2 += __shfl_xor_sync(0xffffffffu, s2, o);
            }
            float mean = s * inv256;
            float var  = fmaf(-mean, mean, s2 * inv256);
            float rstd = rsqrtf(var + LN_EPS);

            float* orow = out + ((size_t)t * NN + gr0 + row0 + r) * HH;
#pragma unroll
            for (int q = 0; q < 4; ++q) {
                int c = colb + 64 * q;
                float4 o4;
                o4.x = (v[4 * q + 0] - mean) * rstd * sLNw[c + 0] + sLNb[c + 0];
                o4.y = (v[4 * q + 1] - mean) * rstd * sLNw[c + 1] + sLNb[c + 1];
                o4.z = (v[4 * q + 2] - mean) * rstd * sLNw[c + 2] + sLNb[c + 2];
                o4.w = (v[4 * q + 3] - mean) * rstd * sLNw[c + 3] + sLNb[c + 3];
                *(float4*)(orow + c) = o4;
            }
        }
        // next iteration's x-load + its __syncthreads separate these h writes
        // from the next GEMM's reads
    }
}

#define SMEM_BYTES ((MT * ASTR + 2 * KCH * HH + 3 * HH) * (int)sizeof(float))  // 167936

extern "C" void kernel_launch(void* const* d_in, const int* in_sizes, int n_in,
                              void* d_out, int out_size) {
    const float* X    = (const float*)d_in[0];
    const float* W_ih = (const float*)d_in[1];
    const float* W_hh = (const float*)d_in[2];
    const float* b_ih = (const float*)d_in[3];
    const float* b_hh = (const float*)d_in[4];
    const float* ln_w = (const float*)d_in[5];
    const float* ln_b = (const float*)d_in[6];
    float* out = (float*)d_out;

    cudaFuncSetAttribute(rnn_kernel, cudaFuncAttributeMaxDynamicSharedMemorySize, SMEM_BYTES);

    prep_kernel<<<64, NTH>>>(W_ih, W_hh, b_ih, b_hh);
    rnn_kernel<<<NCTA, NTH, SMEM_BYTES>>>(X, ln_w, ln_b, out);
}